// round 8
// baseline (speedup 1.0000x reference)
#include <cuda_runtime.h>
#include <cstdint>
#include <cstddef>

// Correlation: out[b, ix*21+iy, h, w] = sum_c f1[b,c,h,w] * f2[b,c,h+2ix-20, w+2iy-20]
// B=4, C=128, H=96, W=192, D=20, stride 2 -> 441 offsets.
//
// Parity FIR: out[u][j] += f1[u] * f2p[u+j-10]; smem slot s = u+j (s in [10,105]
// holds image data, rest zero pad). Tap split j = 12*jh + jj (12%4==0 keeps the
// window base float4-aligned -> all register indices compile-time; jh=1 top 3
// taps are garbage computed into zero pad, never stored).
// R8 changes: staging pointers/slots precomputed ONCE per thread (channel stride
// 96*192 identical for f1/f2 -> per-chunk advance is one pointer add), and pad
// slots are never re-stored (smem zeroed once). Kills the per-chunk div/mod ALU
// and shrinks barrier STS-drain.

#define CC        2                    // channels per smem chunk
#define NTHR      672                  // 7 q * 2 jh * 2 p * 24 t
#define S1_FLOATS (CC * 2 * 96)        // 384  [c][parity][96]
#define S2_FLOATS (CC * 7 * 2 * 120)   // 3360 [c][q][parity][120]
#define BUF_FLOATS (S1_FLOATS + S2_FLOATS)   // 3744 floats
#define S2OFF     S1_FLOATS
#define TOTAL_F2  (CC * 96 + CC * 7 * 120)   // 1872 float2 slots per chunk
#define NL        3                    // ceil(1872/672)
#define CH_STRIDE (96 * 192)           // floats per channel (both tensors)

__global__ void __launch_bounds__(NTHR, 1)
corr_kernel(const float* __restrict__ f1, const float* __restrict__ f2,
            float* __restrict__ out)
{
    extern __shared__ float smem[];

    const int h   = blockIdx.x;   // 0..95
    const int b   = blockIdx.y;   // 0..3
    const int ixg = blockIdx.z;   // 0..2
    const int tid = threadIdx.x;

    const int q   = tid / 96;          // 0..6 : ix within group
    const int r0  = tid % 96;
    const int jh  = r0 / 48;           // tap half: j = 12*jh + jj
    const int r1  = r0 % 48;
    const int p   = r1 / 24;           // parity of w
    const int t   = r1 % 24;           // u-tile
    const int u0  = 4 * t;
    const int ix     = ixg * 7 + q;
    const int h2base = h + 14 * ixg - 20;
    const int wb12   = u0 + 12 * jh;   // window base slot (float4-aligned)

    // Zero both buffers once: pad slots (s<10, s>105, OOB rows) are position-
    // fixed across channels and never re-stored afterwards.
    for (int i = tid; i < 2 * BUF_FLOATS; i += NTHR) smem[i] = 0.0f;

    // ---- one-time staging precompute: NL (gptr, smem-slot) pairs ----
    const float* gp[NL];
    int se[NL];
    #pragma unroll
    for (int i = 0; i < NL; i++) {
        se[i] = -1;
        gp[i] = f1;   // dummy init
        int idx = tid + i * NTHR;
        if (idx < TOTAL_F2) {
            if (idx < CC * 96) {                     // f1 slot
                int c = idx / 96;
                int u = idx - c * 96;
                gp[i] = f1 + ((size_t)(b * 128 + c) * 96 + h) * 192 + 2 * u;
                se[i] = (c * 2) * 96 + u;            // < S2OFF -> odd delta 96
            } else {                                  // f2 slot
                int t2 = idx - CC * 96;
                int c  = t2 / 840;
                int rr = t2 - c * 840;
                int qq = rr / 120;
                int s  = rr - qq * 120;
                int h2 = h2base + 2 * qq;
                if (s >= 10 && s <= 105 && (unsigned)h2 < 96u) {
                    gp[i] = f2 + ((size_t)(b * 128 + c) * 96 + h2) * 192 + (2 * s - 20);
                    se[i] = S2OFF + ((c * 7 + qq) * 2) * 120 + s;   // odd delta 120
                }
            }
        }
    }

    __syncthreads();   // zero-init visible before first stores

    float acc[48];
    #pragma unroll
    for (int i = 0; i < 48; i++) acc[i] = 0.0f;

    float2 v[NL];

    // prologue: chunk 0
    #pragma unroll
    for (int i = 0; i < NL; i++)
        if (se[i] >= 0) v[i] = *reinterpret_cast<const float2*>(gp[i]);
    #pragma unroll
    for (int i = 0; i < NL; i++)
        if (se[i] >= 0) {
            int d = (se[i] < S2OFF) ? 96 : 120;
            smem[se[i]]     = v[i].x;
            smem[se[i] + d] = v[i].y;
        }
    __syncthreads();

    const int NCHUNK = 128 / CC;   // 64
    #pragma unroll 1
    for (int cc = 0; cc < NCHUNK; cc++) {
        const float* cur = smem + (cc & 1) * BUF_FLOATS;
        float*       nxt = smem + ((cc + 1) & 1) * BUF_FLOATS;

        if (cc + 1 < NCHUNK) {       // issue next chunk's LDGs early
            #pragma unroll
            for (int i = 0; i < NL; i++)
                if (se[i] >= 0) {
                    gp[i] += CC * CH_STRIDE;
                    v[i] = *reinterpret_cast<const float2*>(gp[i]);
                }
        }

        #pragma unroll
        for (int c = 0; c < CC; c++) {
            float4 v1 = *reinterpret_cast<const float4*>(cur + (c * 2 + p) * 96 + u0);
            const float4* wp = reinterpret_cast<const float4*>(
                cur + S2OFF + ((c * 7 + q) * 2 + p) * 120 + wb12);
            float4 W0 = wp[0], W1 = wp[1], W2 = wp[2], W3 = wp[3];
            float w[16] = {W0.x, W0.y, W0.z, W0.w, W1.x, W1.y, W1.z, W1.w,
                           W2.x, W2.y, W2.z, W2.w, W3.x, W3.y, W3.z, W3.w};
            float a[4] = {v1.x, v1.y, v1.z, v1.w};
            #pragma unroll
            for (int k = 0; k < 4; k++) {
                float fv = a[k];
                #pragma unroll
                for (int jj = 0; jj < 12; jj++)
                    acc[k * 12 + jj] = fmaf(fv, w[k + jj], acc[k * 12 + jj]);
            }
        }

        if (cc + 1 < NCHUNK) {
            #pragma unroll
            for (int i = 0; i < NL; i++)
                if (se[i] >= 0) {
                    int d = (se[i] < S2OFF) ? 96 : 120;
                    nxt[se[i]]     = v[i].x;
                    nxt[se[i] + d] = v[i].y;
                }
        }
        __syncthreads();
    }

    // store: j = 12*jh + jj; jh=0 -> jj 0..11, jh=1 -> jj 0..8 (j <= 20)
    const int njj   = jh ? 9 : 12;
    const int wbase = 2 * u0 + p;
    size_t obase = (((size_t)b * 441 + (size_t)ix * 21 + 12 * jh) * 96 + h) * 192;
    #pragma unroll
    for (int jj = 0; jj < 12; jj++) {
        if (jj < njj) {
            size_t ob = obase + (size_t)jj * (96 * 192) + wbase;
            #pragma unroll
            for (int k = 0; k < 4; k++)
                out[ob + 2 * k] = acc[k * 12 + jj];
        }
    }
}

extern "C" void kernel_launch(void* const* d_in, const int* in_sizes, int n_in,
                              void* d_out, int out_size)
{
    const float* f1 = (const float*)d_in[0];
    const float* f2 = (const float*)d_in[1];
    float* out = (float*)d_out;

    size_t smem_bytes = (size_t)2 * BUF_FLOATS * sizeof(float);   // 29952 B
    cudaFuncSetAttribute(corr_kernel, cudaFuncAttributeMaxDynamicSharedMemorySize,
                         (int)smem_bytes);

    dim3 grid(96, 4, 3);   // (h, b, ix-group)
    corr_kernel<<<grid, NTHR, smem_bytes>>>(f1, f2, out);
}

// round 9
// speedup vs baseline: 1.1978x; 1.1978x over previous
#include <cuda_runtime.h>
#include <cstdint>
#include <cstddef>

// Correlation: out[b, ix*21+iy, h, w] = sum_c f1[b,c,h,w] * f2[b,c,h+2ix-20, w+2iy-20]
// B=4, C=128, H=96, W=192, D=20, stride 2 -> 441 offsets.
//
// Parity FIR: out[u][j] += f1[u] * f2p[u+j-10]; smem slot s = u+j, s in [10,105]
// holds data, rest zero. SMALL-CTA design: 192 threads (2jh x 2q x 2p x 24t),
// 44 accs, <=85 regs -> 4 CTAs/SM; independent barriers destagger so staging
// bubbles are covered cross-CTA. Taps split 11/10 (jh warp-uniform, outermost):
// jh=0 handles j 0..10 (4 window float4s, rel k+jj), jh=1 handles j 11..20
// (5 window float4s from base u0+8, rel k+jj+3); jh=1 jj=10 is garbage, never
// stored. Staging state = 8 regs (u32 float-offset with tensor-select bit 24).

#define NTHR   192
#define CC     2
#define S1F    (CC * 2 * 96)            // 384  [c][p][96]
#define S2F    (CC * 2 * 2 * 120)       // 960  [c][q][p][120]
#define BUF    (S1F + S2F)              // 1344 floats
#define S2OFF  S1F
#define TOTAL_F2 (CC * (96 + 2 * 120))  // 672 float2 slots per chunk
#define NL     4                        // ceil(672/192)
#define CH_STRIDE 18432                 // 96*192 floats per channel (both tensors)
#define SEL_BIT   (1u << 24)            // goff bit: 0 = f1, 1 = f2
#define INVALID   0xFFFFFFFFu

__global__ void __launch_bounds__(NTHR, 4)
corr_kernel(const float* __restrict__ f1, const float* __restrict__ f2,
            float* __restrict__ out)
{
    extern __shared__ float smem[];

    const int h   = blockIdx.x;   // 0..95
    const int b   = blockIdx.y;   // 0..3
    const int ixg = blockIdx.z;   // 0..10 : ix pair {2*ixg, 2*ixg+1}
    const int tid = threadIdx.x;

    const int jh = tid / 96;           // warp-uniform (96 = 3 warps)
    const int r0 = tid % 96;
    const int q  = r0 / 48;            // 0..1 : ix within pair
    const int r1 = r0 % 48;
    const int p  = r1 / 24;            // parity of w
    const int t  = r1 % 24;            // u-tile
    const int u0 = 4 * t;
    const int ix = 2 * ixg + q;        // 21 is a dummy slice (computed, not stored)
    const int h2base = h + 4 * ixg - 20;
    const int wslot  = u0 + (jh ? 8 : 0);   // window base slot (float4-aligned)

    // zero both buffers once: pad slots are fixed positions, never re-stored
    for (int i = tid; i < 2 * BUF; i += NTHR) smem[i] = 0.0f;

    // ---- staging precompute: NL slots as (goff u32 + sel bit, smem idx) ----
    uint32_t goff[NL], se[NL];
    #pragma unroll
    for (int i = 0; i < NL; i++) {
        se[i] = INVALID;
        goff[i] = 0;
        int idx = tid + i * NTHR;
        if (idx < TOTAL_F2) {
            if (idx < CC * 96) {                       // f1 slot
                int c = idx / 96;
                int u = idx - c * 96;
                goff[i] = (uint32_t)(((b * 128 + c) * 96 + h) * 192 + 2 * u);
                se[i]   = (uint32_t)((c * 2 + 0) * 96 + u);        // x->se, y->se+96
            } else {                                    // f2 slot
                int t2 = idx - CC * 96;
                int c  = t2 / 240;
                int rr = t2 - c * 240;
                int qq = rr / 120;
                int s  = rr - qq * 120;
                int h2 = h2base + 2 * qq;
                if (s >= 10 && s <= 105 && (unsigned)h2 < 96u) {
                    goff[i] = (uint32_t)(((b * 128 + c) * 96 + h2) * 192 + (2 * s - 20))
                              | SEL_BIT;
                    se[i]   = (uint32_t)(S2OFF + ((c * 2 + qq) * 2 + 0) * 120 + s);
                }
            }
        }
    }

    auto stage = [&](float* nxt) {
        #pragma unroll
        for (int i = 0; i < NL; i++) {
            if (se[i] != INVALID) {
                uint32_t go = goff[i];
                const float* src = ((go & SEL_BIT) ? f2 : f1) + (go & (SEL_BIT - 1u));
                float2 val = *reinterpret_cast<const float2*>(src);
                goff[i] = go + CC * CH_STRIDE;          // no carry into bit 24
                int d = (se[i] < (uint32_t)S2OFF) ? 96 : 120;
                nxt[se[i]]     = val.x;                  // even parity
                nxt[se[i] + d] = val.y;                  // odd parity
            }
        }
    };

    float acc[44];                     // [k 0..3][jj 0..10]
    #pragma unroll
    for (int i = 0; i < 44; i++) acc[i] = 0.0f;

    __syncthreads();                   // zero-init visible
    stage(smem);                       // chunk 0 -> buffer 0
    __syncthreads();

    const int NCHUNK = 128 / CC;       // 64
    #pragma unroll 1
    for (int cc = 0; cc < NCHUNK; cc++) {
        const float* cur = smem + (cc & 1) * BUF;
        float*       nxt = smem + ((cc + 1) & 1) * BUF;

        #pragma unroll
        for (int c = 0; c < CC; c++) {
            float4 v1 = *reinterpret_cast<const float4*>(cur + (c * 2 + p) * 96 + u0);
            const float4* wp = reinterpret_cast<const float4*>(
                cur + S2OFF + ((c * 2 + q) * 2 + p) * 120 + wslot);
            float a[4] = {v1.x, v1.y, v1.z, v1.w};
            if (jh == 0) {
                // j = jj (0..10): slots u0+k+jj, rel k+jj in [0,13]
                float4 W0 = wp[0], W1 = wp[1], W2 = wp[2], W3 = wp[3];
                float w[16] = {W0.x, W0.y, W0.z, W0.w, W1.x, W1.y, W1.z, W1.w,
                               W2.x, W2.y, W2.z, W2.w, W3.x, W3.y, W3.z, W3.w};
                #pragma unroll
                for (int k = 0; k < 4; k++)
                    #pragma unroll
                    for (int jj = 0; jj < 11; jj++)
                        acc[k * 11 + jj] = fmaf(a[k], w[k + jj], acc[k * 11 + jj]);
            } else {
                // j = 11+jj: slots u0+k+11+jj, base u0+8 -> rel k+jj+3 in [3,16]
                float4 W0 = wp[0], W1 = wp[1], W2 = wp[2], W3 = wp[3], W4 = wp[4];
                float w[20] = {W0.x, W0.y, W0.z, W0.w, W1.x, W1.y, W1.z, W1.w,
                               W2.x, W2.y, W2.z, W2.w, W3.x, W3.y, W3.z, W3.w,
                               W4.x, W4.y, W4.z, W4.w};
                #pragma unroll
                for (int k = 0; k < 4; k++)
                    #pragma unroll
                    for (int jj = 0; jj < 11; jj++)
                        acc[k * 11 + jj] = fmaf(a[k], w[k + jj + 3], acc[k * 11 + jj]);
            }
        }

        if (cc + 1 < NCHUNK) stage(nxt);   // bubble covered by other CTAs
        __syncthreads();
    }

    // store: jh=0 -> j 0..10 (11 taps), jh=1 -> j 11..20 (10 taps, jj=10 garbage)
    if (ix < 21) {
        const int njj = jh ? 10 : 11;
        size_t obase = (((size_t)b * 441 + (size_t)ix * 21 + 11 * jh) * 96 + h) * 192
                       + 2 * u0 + p;
        #pragma unroll
        for (int jj = 0; jj < 11; jj++) {
            if (jj < njj) {
                size_t ob = obase + (size_t)jj * CH_STRIDE;
                #pragma unroll
                for (int k = 0; k < 4; k++)
                    out[ob + 2 * k] = acc[k * 11 + jj];
            }
        }
    }
}

extern "C" void kernel_launch(void* const* d_in, const int* in_sizes, int n_in,
                              void* d_out, int out_size)
{
    const float* f1 = (const float*)d_in[0];
    const float* f2 = (const float*)d_in[1];
    float* out = (float*)d_out;

    size_t smem_bytes = (size_t)2 * BUF * sizeof(float);   // 10752 B
    cudaFuncSetAttribute(corr_kernel, cudaFuncAttributeMaxDynamicSharedMemorySize,
                         (int)smem_bytes);

    dim3 grid(96, 4, 11);   // (h, b, ix-pair)
    corr_kernel<<<grid, NTHR, smem_bytes>>>(f1, f2, out);
}